// round 1
// baseline (speedup 1.0000x reference)
#include <cuda_runtime.h>

// Problem constants
#define BT    32          // B*T
#define NN    512         // nodes
#define DD    512         // model dim
#define KH    8           // heads
#define DH    64          // head dim
#define EMBD  64          // node embedding dim
#define D4    2048        // 4*D
#define MROWS (BT*NN)     // 16384 rows

// -------- scratch (device globals: allocation-free) --------
__device__ float g_bias[NN * NN];                       //   1 MB
__device__ float g_xn  [MROWS * DD];                    //  32 MB
__device__ float g_q   [MROWS * DD];
__device__ float g_k   [MROWS * DD];
__device__ float g_v   [MROWS * DD];
__device__ float g_scores[(size_t)BT * KH * NN * NN];   // 256 MB
__device__ float g_o   [MROWS * DD];
__device__ float g_x1  [MROWS * DD];
__device__ float g_x1n [MROWS * DD];
__device__ float g_h   [(size_t)MROWS * D4];            // 128 MB

// ============================================================
// Graph bias: bias[n,m] = alpha*softmax_row(relu(E E^T))[n,m]
//                       + beta*lap[n,m] + (lap[n,m]!=0 ? 0 : -1e9)
// one block per row n, 256 threads (2 cols each)
// ============================================================
__global__ void bias_kernel(const float* __restrict__ E,
                            const float* __restrict__ lap,
                            const float* __restrict__ alpha_p,
                            const float* __restrict__ beta_p,
                            float* __restrict__ bias) {
    int n = blockIdx.x;
    int t = threadIdx.x;
    __shared__ float en[EMBD];
    __shared__ float red[256];
    if (t < EMBD) en[t] = E[n * EMBD + t];
    __syncthreads();

    int m0 = t, m1 = t + 256;
    float s0 = 0.f, s1 = 0.f;
#pragma unroll 8
    for (int e = 0; e < EMBD; e++) {
        float qe = en[e];
        s0 += qe * E[m0 * EMBD + e];
        s1 += qe * E[m1 * EMBD + e];
    }
    s0 = fmaxf(s0, 0.f);
    s1 = fmaxf(s1, 0.f);

    red[t] = fmaxf(s0, s1);
    __syncthreads();
    for (int off = 128; off > 0; off >>= 1) {
        if (t < off) red[t] = fmaxf(red[t], red[t + off]);
        __syncthreads();
    }
    float mx = red[0];
    __syncthreads();
    float e0 = __expf(s0 - mx), e1 = __expf(s1 - mx);
    red[t] = e0 + e1;
    __syncthreads();
    for (int off = 128; off > 0; off >>= 1) {
        if (t < off) red[t] += red[t + off];
        __syncthreads();
    }
    float inv = 1.f / red[0];

    float alpha = *alpha_p, beta = *beta_p;
    float l0 = lap[n * NN + m0], l1 = lap[n * NN + m1];
    bias[n * NN + m0] = alpha * e0 * inv + beta * l0 + (l0 != 0.f ? 0.f : -1e9f);
    bias[n * NN + m1] = alpha * e1 * inv + beta * l1 + (l1 != 0.f ? 0.f : -1e9f);
}

// ============================================================
// LayerNorm over last dim (512). one block per row, 256 threads
// ============================================================
__global__ void ln_kernel(const float* __restrict__ x,
                          const float* __restrict__ g,
                          const float* __restrict__ b,
                          float* __restrict__ y) {
    int r = blockIdx.x;
    int t = threadIdx.x;
    const float* xr = x + (size_t)r * DD;
    float v0 = xr[t], v1 = xr[t + 256];
    __shared__ float red[256];
    red[t] = v0 + v1;
    __syncthreads();
    for (int off = 128; off > 0; off >>= 1) {
        if (t < off) red[t] += red[t + off];
        __syncthreads();
    }
    float mu = red[0] * (1.f / DD);
    __syncthreads();
    float d0 = v0 - mu, d1 = v1 - mu;
    red[t] = d0 * d0 + d1 * d1;
    __syncthreads();
    for (int off = 128; off > 0; off >>= 1) {
        if (t < off) red[t] += red[t + off];
        __syncthreads();
    }
    float rs = rsqrtf(red[0] * (1.f / DD) + 1e-5f);
    float* yr = y + (size_t)r * DD;
    yr[t]       = d0 * rs * g[t]       + b[t];
    yr[t + 256] = d1 * rs * g[t + 256] + b[t + 256];
}

// ============================================================
// Row softmax over 512 elements. one block per row, 256 threads
// ============================================================
__global__ void softmax_kernel(float* __restrict__ S) {
    size_t r = blockIdx.x;
    float* row = S + r * NN;
    int t = threadIdx.x;
    float v0 = row[t], v1 = row[t + 256];
    __shared__ float red[256];
    red[t] = fmaxf(v0, v1);
    __syncthreads();
    for (int off = 128; off > 0; off >>= 1) {
        if (t < off) red[t] = fmaxf(red[t], red[t + off]);
        __syncthreads();
    }
    float mx = red[0];
    __syncthreads();
    float e0 = __expf(v0 - mx), e1 = __expf(v1 - mx);
    red[t] = e0 + e1;
    __syncthreads();
    for (int off = 128; off > 0; off >>= 1) {
        if (t < off) red[t] += red[t + off];
        __syncthreads();
    }
    float inv = 1.f / red[0];
    row[t]       = e0 * inv;
    row[t + 256] = e1 * inv;
}

// ============================================================
// Tiled SGEMM: C[M,Nd] = A[M,Kd] @ B[Nd,Kd]^T + bias[Nd]
//              (+ residual, + relu).  64x64 tile, BK=16,
//              256 threads, 4x4 per thread.
// lda = Kd, ldb = Kd, ldc = ld(res) = Nd (all compact row-major)
// ============================================================
template <bool RELU, bool RESID>
__global__ void gemm_nt(const float* __restrict__ A, const float* __restrict__ B,
                        const float* __restrict__ bias, const float* __restrict__ res,
                        float* __restrict__ C, int M, int Nd, int Kd) {
    __shared__ float As[16][68];
    __shared__ float Bs[16][68];
    int t = threadIdx.x;
    int tx = t & 15, ty = t >> 4;
    int m0 = blockIdx.y * 64, n0 = blockIdx.x * 64;
    int lrow = t >> 2;            // 0..63
    int lcol4 = (t & 3) * 4;      // 0,4,8,12
    const float* Aptr = A + (size_t)(m0 + lrow) * Kd + lcol4;
    const float* Bptr = B + (size_t)(n0 + lrow) * Kd + lcol4;

    float acc[4][4] = {};
    for (int k0 = 0; k0 < Kd; k0 += 16) {
        float4 av = *(const float4*)(Aptr + k0);
        float4 bv = *(const float4*)(Bptr + k0);
        As[lcol4 + 0][lrow] = av.x; As[lcol4 + 1][lrow] = av.y;
        As[lcol4 + 2][lrow] = av.z; As[lcol4 + 3][lrow] = av.w;
        Bs[lcol4 + 0][lrow] = bv.x; Bs[lcol4 + 1][lrow] = bv.y;
        Bs[lcol4 + 2][lrow] = bv.z; Bs[lcol4 + 3][lrow] = bv.w;
        __syncthreads();
#pragma unroll
        for (int kk = 0; kk < 16; kk++) {
            float4 a = *(const float4*)&As[kk][ty * 4];
            float4 bb = *(const float4*)&Bs[kk][tx * 4];
            float ar[4] = {a.x, a.y, a.z, a.w};
            float br[4] = {bb.x, bb.y, bb.z, bb.w};
#pragma unroll
            for (int i = 0; i < 4; i++)
#pragma unroll
                for (int j = 0; j < 4; j++) acc[i][j] += ar[i] * br[j];
        }
        __syncthreads();
    }
#pragma unroll
    for (int i = 0; i < 4; i++) {
        int row = m0 + ty * 4 + i;
#pragma unroll
        for (int j = 0; j < 4; j++) {
            int col = n0 + tx * 4 + j;
            float c = acc[i][j] + bias[col];
            if (RESID) c += res[(size_t)row * Nd + col];
            if (RELU) c = fmaxf(c, 0.f);
            C[(size_t)row * Nd + col] = c;
        }
    }
}

// ============================================================
// Attention scores: per z=(bt,head): S = Q @ K^T * 0.125 + bias
// Q,K rows strided by DD (head slice of width 64). 64x64 tiles.
// ============================================================
__global__ void attn_scores(const float* __restrict__ Q, const float* __restrict__ Kt,
                            const float* __restrict__ bias, float* __restrict__ S) {
    __shared__ float As[16][68];
    __shared__ float Bs[16][68];
    int z = blockIdx.z;
    int bt = z >> 3, h = z & 7;
    const float* Ab = Q + (size_t)bt * NN * DD + h * DH;
    const float* Bb = Kt + (size_t)bt * NN * DD + h * DH;
    float* Cb = S + (size_t)z * NN * NN;

    int t = threadIdx.x;
    int tx = t & 15, ty = t >> 4;
    int m0 = blockIdx.y * 64, n0 = blockIdx.x * 64;
    int lrow = t >> 2, lcol4 = (t & 3) * 4;
    const float* Aptr = Ab + (size_t)(m0 + lrow) * DD + lcol4;
    const float* Bptr = Bb + (size_t)(n0 + lrow) * DD + lcol4;

    float acc[4][4] = {};
    for (int k0 = 0; k0 < DH; k0 += 16) {
        float4 av = *(const float4*)(Aptr + k0);
        float4 bv = *(const float4*)(Bptr + k0);
        As[lcol4 + 0][lrow] = av.x; As[lcol4 + 1][lrow] = av.y;
        As[lcol4 + 2][lrow] = av.z; As[lcol4 + 3][lrow] = av.w;
        Bs[lcol4 + 0][lrow] = bv.x; Bs[lcol4 + 1][lrow] = bv.y;
        Bs[lcol4 + 2][lrow] = bv.z; Bs[lcol4 + 3][lrow] = bv.w;
        __syncthreads();
#pragma unroll
        for (int kk = 0; kk < 16; kk++) {
            float4 a = *(const float4*)&As[kk][ty * 4];
            float4 bb = *(const float4*)&Bs[kk][tx * 4];
            float ar[4] = {a.x, a.y, a.z, a.w};
            float br[4] = {bb.x, bb.y, bb.z, bb.w};
#pragma unroll
            for (int i = 0; i < 4; i++)
#pragma unroll
                for (int j = 0; j < 4; j++) acc[i][j] += ar[i] * br[j];
        }
        __syncthreads();
    }
#pragma unroll
    for (int i = 0; i < 4; i++) {
        int row = m0 + ty * 4 + i;
#pragma unroll
        for (int j = 0; j < 4; j++) {
            int col = n0 + tx * 4 + j;
            Cb[(size_t)row * NN + col] = acc[i][j] * 0.125f + bias[row * NN + col];
        }
    }
}

// ============================================================
// Attention AV: per z: O[n,e] = sum_m attn[n,m] * V[m,e]
// A: [512,512] compact. B (V): rows strided DD, head slice 64 wide.
// One 64x64 tile covers all of dh; grid (mtiles=8, z=256).
// ============================================================
__global__ void attn_av(const float* __restrict__ S, const float* __restrict__ V,
                        float* __restrict__ O) {
    __shared__ float As[16][68];
    __shared__ float Bs[16][68];
    int z = blockIdx.y;
    int bt = z >> 3, h = z & 7;
    const float* Ab = S + (size_t)z * NN * NN;
    const float* Bb = V + (size_t)bt * NN * DD + h * DH;
    float* Cb = O + (size_t)bt * NN * DD + h * DH;

    int t = threadIdx.x;
    int tx = t & 15, ty = t >> 4;
    int m0 = blockIdx.x * 64;
    int lrow = t >> 2, lcol4 = (t & 3) * 4;  // A tile: 64 rows x 16 k
    int brow = t >> 4, bcol4 = (t & 15) * 4; // B tile: 16 k x 64 cols

    const float* Aptr = Ab + (size_t)(m0 + lrow) * NN + lcol4;

    float acc[4][4] = {};
    for (int k0 = 0; k0 < NN; k0 += 16) {
        float4 av = *(const float4*)(Aptr + k0);
        float4 bv = *(const float4*)(Bb + (size_t)(k0 + brow) * DD + bcol4);
        As[lcol4 + 0][lrow] = av.x; As[lcol4 + 1][lrow] = av.y;
        As[lcol4 + 2][lrow] = av.z; As[lcol4 + 3][lrow] = av.w;
        *(float4*)&Bs[brow][bcol4] = bv;
        __syncthreads();
#pragma unroll
        for (int kk = 0; kk < 16; kk++) {
            float4 a = *(const float4*)&As[kk][ty * 4];
            float4 bb = *(const float4*)&Bs[kk][tx * 4];
            float ar[4] = {a.x, a.y, a.z, a.w};
            float br[4] = {bb.x, bb.y, bb.z, bb.w};
#pragma unroll
            for (int i = 0; i < 4; i++)
#pragma unroll
                for (int j = 0; j < 4; j++) acc[i][j] += ar[i] * br[j];
        }
        __syncthreads();
    }
#pragma unroll
    for (int i = 0; i < 4; i++) {
        int row = m0 + ty * 4 + i;
#pragma unroll
        for (int j = 0; j < 4; j++) {
            int col = tx * 4 + j;
            Cb[(size_t)row * DD + col] = acc[i][j];
        }
    }
}

// ============================================================
extern "C" void kernel_launch(void* const* d_in, const int* in_sizes, int n_in,
                              void* d_out, int out_size) {
    const float* x    = (const float*)d_in[0];
    const float* lap  = (const float*)d_in[1];
    const float* emb  = (const float*)d_in[2];
    const float* Wq   = (const float*)d_in[3];
    const float* bq   = (const float*)d_in[4];
    const float* Wk   = (const float*)d_in[5];
    const float* bk   = (const float*)d_in[6];
    const float* Wv   = (const float*)d_in[7];
    const float* bv   = (const float*)d_in[8];
    const float* ln1g = (const float*)d_in[9];
    const float* ln1b = (const float*)d_in[10];
    const float* ln2g = (const float*)d_in[11];
    const float* ln2b = (const float*)d_in[12];
    const float* alpha = (const float*)d_in[13];
    const float* beta  = (const float*)d_in[14];
    const float* Wo   = (const float*)d_in[15];
    const float* bo   = (const float*)d_in[16];
    const float* W1   = (const float*)d_in[17];
    const float* b1   = (const float*)d_in[18];
    const float* W2   = (const float*)d_in[19];
    const float* b2   = (const float*)d_in[20];
    float* out = (float*)d_out;

    float *p_bias, *p_xn, *p_q, *p_k, *p_v, *p_s, *p_o, *p_x1, *p_x1n, *p_h;
    cudaGetSymbolAddress((void**)&p_bias, g_bias);
    cudaGetSymbolAddress((void**)&p_xn, g_xn);
    cudaGetSymbolAddress((void**)&p_q, g_q);
    cudaGetSymbolAddress((void**)&p_k, g_k);
    cudaGetSymbolAddress((void**)&p_v, g_v);
    cudaGetSymbolAddress((void**)&p_s, g_scores);
    cudaGetSymbolAddress((void**)&p_o, g_o);
    cudaGetSymbolAddress((void**)&p_x1, g_x1);
    cudaGetSymbolAddress((void**)&p_x1n, g_x1n);
    cudaGetSymbolAddress((void**)&p_h, g_h);

    // 1. graph bias matrix [N,N]
    bias_kernel<<<NN, 256>>>(emb, lap, alpha, beta, p_bias);
    // 2. LN1
    ln_kernel<<<MROWS, 256>>>(x, ln1g, ln1b, p_xn);
    // 3. Q/K/V projections
    dim3 g512(DD / 64, MROWS / 64);
    gemm_nt<false, false><<<g512, 256>>>(p_xn, Wq, bq, nullptr, p_q, MROWS, DD, DD);
    gemm_nt<false, false><<<g512, 256>>>(p_xn, Wk, bk, nullptr, p_k, MROWS, DD, DD);
    gemm_nt<false, false><<<g512, 256>>>(p_xn, Wv, bv, nullptr, p_v, MROWS, DD, DD);
    // 4. scores = QK^T/8 + bias, per (bt,head)
    attn_scores<<<dim3(NN / 64, NN / 64, BT * KH), 256>>>(p_q, p_k, p_bias, p_s);
    // 5. softmax rows
    softmax_kernel<<<BT * KH * NN, 256>>>(p_s);
    // 6. O = attn @ V
    attn_av<<<dim3(NN / 64, BT * KH), 256>>>(p_s, p_v, p_o);
    // 7. x1 = x + O @ Wo^T + bo
    gemm_nt<false, true><<<g512, 256>>>(p_o, Wo, bo, x, p_x1, MROWS, DD, DD);
    // 8. LN2
    ln_kernel<<<MROWS, 256>>>(p_x1, ln2g, ln2b, p_x1n);
    // 9. h = relu(x1n @ W1^T + b1)
    gemm_nt<true, false><<<dim3(D4 / 64, MROWS / 64), 256>>>(p_x1n, W1, b1, nullptr, p_h, MROWS, D4, DD);
    // 10. out = x1 + h @ W2^T + b2
    gemm_nt<false, true><<<g512, 256>>>(p_h, W2, b2, p_x1, out, MROWS, DD, D4);
}

// round 3
// speedup vs baseline: 1.1700x; 1.1700x over previous
#include <cuda_runtime.h>

// Problem constants
#define BT    32          // B*T
#define NN    512         // nodes
#define DD    512         // model dim
#define KH    8           // heads
#define DH    64          // head dim
#define EMBD  64          // node embedding dim
#define D4    2048        // 4*D
#define MROWS (BT*NN)     // 16384 rows

#define EPI_NONE  0
#define EPI_BIAS  1
#define EPI_SCORE 2

// -------- scratch (device globals: allocation-free) --------
__device__ float g_bias[NN * NN];                       //   1 MB
__device__ float g_xn  [MROWS * DD];                    //  32 MB
__device__ float g_q   [MROWS * DD];
__device__ float g_k   [MROWS * DD];
__device__ float g_v   [MROWS * DD];
__device__ float g_scores[(size_t)BT * KH * NN * NN];   // 256 MB
__device__ float g_o   [MROWS * DD];
__device__ float g_x1  [MROWS * DD];
__device__ float g_x1n [MROWS * DD];
__device__ float g_h   [(size_t)MROWS * D4];            // 128 MB

// ============================================================
// Graph bias matrix
// ============================================================
__global__ void bias_kernel(const float* __restrict__ E,
                            const float* __restrict__ lap,
                            const float* __restrict__ alpha_p,
                            const float* __restrict__ beta_p,
                            float* __restrict__ bias) {
    int n = blockIdx.x;
    int t = threadIdx.x;
    __shared__ float en[EMBD];
    __shared__ float red[256];
    if (t < EMBD) en[t] = E[n * EMBD + t];
    __syncthreads();

    int m0 = t, m1 = t + 256;
    float s0 = 0.f, s1 = 0.f;
#pragma unroll 8
    for (int e = 0; e < EMBD; e++) {
        float qe = en[e];
        s0 += qe * E[m0 * EMBD + e];
        s1 += qe * E[m1 * EMBD + e];
    }
    s0 = fmaxf(s0, 0.f);
    s1 = fmaxf(s1, 0.f);

    red[t] = fmaxf(s0, s1);
    __syncthreads();
    for (int off = 128; off > 0; off >>= 1) {
        if (t < off) red[t] = fmaxf(red[t], red[t + off]);
        __syncthreads();
    }
    float mx = red[0];
    __syncthreads();
    float e0 = __expf(s0 - mx), e1 = __expf(s1 - mx);
    red[t] = e0 + e1;
    __syncthreads();
    for (int off = 128; off > 0; off >>= 1) {
        if (t < off) red[t] += red[t + off];
        __syncthreads();
    }
    float inv = 1.f / red[0];

    float alpha = *alpha_p, beta = *beta_p;
    float l0 = lap[n * NN + m0], l1 = lap[n * NN + m1];
    bias[n * NN + m0] = alpha * e0 * inv + beta * l0 + (l0 != 0.f ? 0.f : -1e9f);
    bias[n * NN + m1] = alpha * e1 * inv + beta * l1 + (l1 != 0.f ? 0.f : -1e9f);
}

// ============================================================
// LayerNorm over last dim (512)
// ============================================================
__global__ void ln_kernel(const float* __restrict__ x,
                          const float* __restrict__ g,
                          const float* __restrict__ b,
                          float* __restrict__ y) {
    int r = blockIdx.x;
    int t = threadIdx.x;
    const float* xr = x + (size_t)r * DD;
    float v0 = xr[t], v1 = xr[t + 256];
    __shared__ float red[256];
    red[t] = v0 + v1;
    __syncthreads();
    for (int off = 128; off > 0; off >>= 1) {
        if (t < off) red[t] += red[t + off];
        __syncthreads();
    }
    float mu = red[0] * (1.f / DD);
    __syncthreads();
    float d0 = v0 - mu, d1 = v1 - mu;
    red[t] = d0 * d0 + d1 * d1;
    __syncthreads();
    for (int off = 128; off > 0; off >>= 1) {
        if (t < off) red[t] += red[t + off];
        __syncthreads();
    }
    float rs = rsqrtf(red[0] * (1.f / DD) + 1e-5f);
    float* yr = y + (size_t)r * DD;
    yr[t]       = d0 * rs * g[t]       + b[t];
    yr[t + 256] = d1 * rs * g[t + 256] + b[t + 256];
}

// ============================================================
// Row softmax over 512 elements
// ============================================================
__global__ void softmax_kernel(float* __restrict__ S) {
    size_t r = blockIdx.x;
    float* row = S + r * NN;
    int t = threadIdx.x;
    float v0 = row[t], v1 = row[t + 256];
    __shared__ float red[256];
    red[t] = fmaxf(v0, v1);
    __syncthreads();
    for (int off = 128; off > 0; off >>= 1) {
        if (t < off) red[t] = fmaxf(red[t], red[t + off]);
        __syncthreads();
    }
    float mx = red[0];
    __syncthreads();
    float e0 = __expf(v0 - mx), e1 = __expf(v1 - mx);
    red[t] = e0 + e1;
    __syncthreads();
    for (int off = 128; off > 0; off >>= 1) {
        if (t < off) red[t] += red[t + off];
        __syncthreads();
    }
    float inv = 1.f / red[0];
    row[t]       = e0 * inv;
    row[t + 256] = e1 * inv;
}

// ============================================================
// FFMA2-based SGEMM, 128 x BN tile, BK=8, double buffered.
// C[M,Nd] = A[M,Kd] @ op(B) (+ epilogue)
//   B_NT = true : B is [Nd,Kd] row-major (C = A B^T), transposed on load
//   B_NT = false: B is [Kd,Nd] row-major (C = A B), copied directly
// BMODE: 0 = plain (z unused); 1 = attn scores; 2 = attn AV
// ============================================================
union F4u { float4 v; struct { unsigned long long lo, hi; } u; };

__device__ __forceinline__ unsigned long long dup2(float x) {
    unsigned long long r;
    unsigned int xi = __float_as_uint(x);
    asm("mov.b64 %0, {%1, %1};" : "=l"(r) : "r"(xi));
    return r;
}
__device__ __forceinline__ void fma2(unsigned long long& acc,
                                     unsigned long long a, unsigned long long b) {
    asm("fma.rn.f32x2 %0, %1, %2, %0;" : "+l"(acc) : "l"(a), "l"(b));
}
__device__ __forceinline__ float f2lo(unsigned long long u) {
    return __uint_as_float((unsigned int)u);
}
__device__ __forceinline__ float f2hi(unsigned long long u) {
    return __uint_as_float((unsigned int)(u >> 32));
}

template <int BN, int EPI, bool RELU, bool RESID, int BMODE, bool B_NT>
__global__ void __launch_bounds__(256) gemm128(
    const float* __restrict__ A, const float* __restrict__ B,
    const float* __restrict__ biasv, const float* __restrict__ bias2d,
    const float* __restrict__ res, float* __restrict__ C,
    int M, int Nd, int Kd, int lda, int ldb, int ldc) {
    constexpr int CQ = BN / 64;
    __shared__ float As[2][8][132];
    __shared__ float Bs[2][8][BN + 4];

    int z = blockIdx.z;
    if (BMODE == 1) {
        long hb = (long)(z >> 3) * NN * DD + (long)(z & 7) * DH;
        A += hb; B += hb; C += (long)z * NN * NN;
    } else if (BMODE == 2) {
        long hb = (long)(z >> 3) * NN * DD + (long)(z & 7) * DH;
        A += (long)z * NN * NN; B += hb; C += hb;
    }

    int t = threadIdx.x;
    int tx = t & 15, ty = t >> 4;
    int m0 = blockIdx.y * 128, n0 = blockIdx.x * BN;

    // A tile load: 128 rows x 8 k, transpose into As[k][m]
    int arow = t >> 1, acol = (t & 1) * 4;
    const float* Ag = A + (long)(m0 + arow) * lda + acol;

    // B tile load
    bool bpred;
    int brow, bcol;
    const float* Bg;
    if (B_NT) {
        brow = t >> 1; bcol = (t & 1) * 4;
        bpred = (t < 2 * BN);
        Bg = B + (long)(n0 + brow) * ldb + bcol;
    } else {
        constexpr int BQ = BN / 4;
        brow = t / BQ; bcol = (t % BQ) * 4;
        bpred = (t < 2 * BN);
        Bg = B + (long)brow * ldb + (n0 + bcol);
    }

    unsigned long long acc[2][2][CQ][4];
#pragma unroll
    for (int a = 0; a < 2; a++)
#pragma unroll
        for (int b = 0; b < 2; b++)
#pragma unroll
            for (int c = 0; c < CQ; c++)
#pragma unroll
                for (int d = 0; d < 4; d++) acc[a][b][c][d] = 0ull;

    // preload tile 0
    float4 av = *(const float4*)Ag;
    float4 bv = make_float4(0.f, 0.f, 0.f, 0.f);
    if (bpred) bv = *(const float4*)Bg;
    As[0][acol + 0][arow] = av.x; As[0][acol + 1][arow] = av.y;
    As[0][acol + 2][arow] = av.z; As[0][acol + 3][arow] = av.w;
    if (bpred) {
        if (B_NT) {
            Bs[0][bcol + 0][brow] = bv.x; Bs[0][bcol + 1][brow] = bv.y;
            Bs[0][bcol + 2][brow] = bv.z; Bs[0][bcol + 3][brow] = bv.w;
        } else {
            *(float4*)&Bs[0][brow][bcol] = bv;
        }
    }
    __syncthreads();

    int nk = Kd / 8;
    for (int kt = 0; kt < nk; kt++) {
        int buf = kt & 1;
        if (kt + 1 < nk) {
            av = *(const float4*)(Ag + (kt + 1) * 8);
            if (bpred) {
                if (B_NT) bv = *(const float4*)(Bg + (kt + 1) * 8);
                else      bv = *(const float4*)(Bg + (long)(kt + 1) * 8 * ldb);
            }
        }
#pragma unroll
        for (int k = 0; k < 8; k++) {
            F4u a0, a1;
            a0.v = *(const float4*)&As[buf][k][ty * 4];
            a1.v = *(const float4*)&As[buf][k][64 + ty * 4];
            unsigned long long ap[2][2];
            ap[0][0] = a0.u.lo; ap[0][1] = a0.u.hi;
            ap[1][0] = a1.u.lo; ap[1][1] = a1.u.hi;

            float4 b0 = *(const float4*)&Bs[buf][k][tx * 4];
            unsigned long long bd[CQ][4];
            bd[0][0] = dup2(b0.x); bd[0][1] = dup2(b0.y);
            bd[0][2] = dup2(b0.z); bd[0][3] = dup2(b0.w);
            if (CQ == 2) {
                float4 b1 = *(const float4*)&Bs[buf][k][64 + tx * 4];
                bd[1][0] = dup2(b1.x); bd[1][1] = dup2(b1.y);
                bd[1][2] = dup2(b1.z); bd[1][3] = dup2(b1.w);
            }
#pragma unroll
            for (int rq = 0; rq < 2; rq++)
#pragma unroll
                for (int ip = 0; ip < 2; ip++)
#pragma unroll
                    for (int cq = 0; cq < CQ; cq++)
#pragma unroll
                        for (int j = 0; j < 4; j++)
                            fma2(acc[rq][ip][cq][j], ap[rq][ip], bd[cq][j]);
        }
        if (kt + 1 < nk) {
            int nb = buf ^ 1;
            As[nb][acol + 0][arow] = av.x; As[nb][acol + 1][arow] = av.y;
            As[nb][acol + 2][arow] = av.z; As[nb][acol + 3][arow] = av.w;
            if (bpred) {
                if (B_NT) {
                    Bs[nb][bcol + 0][brow] = bv.x; Bs[nb][bcol + 1][brow] = bv.y;
                    Bs[nb][bcol + 2][brow] = bv.z; Bs[nb][bcol + 3][brow] = bv.w;
                } else {
                    *(float4*)&Bs[nb][brow][bcol] = bv;
                }
            }
            __syncthreads();
        }
    }

    // epilogue
#pragma unroll
    for (int rq = 0; rq < 2; rq++)
#pragma unroll
        for (int ip = 0; ip < 2; ip++)
#pragma unroll
            for (int h = 0; h < 2; h++) {
                int row = m0 + rq * 64 + ty * 4 + ip * 2 + h;
#pragma unroll
                for (int cq = 0; cq < CQ; cq++) {
                    int col = n0 + cq * 64 + tx * 4;
                    float4 c;
                    if (h == 0) {
                        c.x = f2lo(acc[rq][ip][cq][0]); c.y = f2lo(acc[rq][ip][cq][1]);
                        c.z = f2lo(acc[rq][ip][cq][2]); c.w = f2lo(acc[rq][ip][cq][3]);
                    } else {
                        c.x = f2hi(acc[rq][ip][cq][0]); c.y = f2hi(acc[rq][ip][cq][1]);
                        c.z = f2hi(acc[rq][ip][cq][2]); c.w = f2hi(acc[rq][ip][cq][3]);
                    }
                    if (EPI == EPI_BIAS) {
                        float4 bb = *(const float4*)&biasv[col];
                        c.x += bb.x; c.y += bb.y; c.z += bb.z; c.w += bb.w;
                    }
                    if (EPI == EPI_SCORE) {
                        float4 bb = *(const float4*)&bias2d[(long)row * NN + col];
                        c.x = c.x * 0.125f + bb.x; c.y = c.y * 0.125f + bb.y;
                        c.z = c.z * 0.125f + bb.z; c.w = c.w * 0.125f + bb.w;
                    }
                    if (RESID) {
                        float4 rr = *(const float4*)&res[(long)row * ldc + col];
                        c.x += rr.x; c.y += rr.y; c.z += rr.z; c.w += rr.w;
                    }
                    if (RELU) {
                        c.x = fmaxf(c.x, 0.f); c.y = fmaxf(c.y, 0.f);
                        c.z = fmaxf(c.z, 0.f); c.w = fmaxf(c.w, 0.f);
                    }
                    *(float4*)&C[(long)row * ldc + col] = c;
                }
            }
}

// ============================================================
extern "C" void kernel_launch(void* const* d_in, const int* in_sizes, int n_in,
                              void* d_out, int out_size) {
    const float* x    = (const float*)d_in[0];
    const float* lap  = (const float*)d_in[1];
    const float* emb  = (const float*)d_in[2];
    const float* Wq   = (const float*)d_in[3];
    const float* bq   = (const float*)d_in[4];
    const float* Wk   = (const float*)d_in[5];
    const float* bk   = (const float*)d_in[6];
    const float* Wv   = (const float*)d_in[7];
    const float* bv   = (const float*)d_in[8];
    const float* ln1g = (const float*)d_in[9];
    const float* ln1b = (const float*)d_in[10];
    const float* ln2g = (const float*)d_in[11];
    const float* ln2b = (const float*)d_in[12];
    const float* alpha = (const float*)d_in[13];
    const float* beta  = (const float*)d_in[14];
    const float* Wo   = (const float*)d_in[15];
    const float* bo   = (const float*)d_in[16];
    const float* W1   = (const float*)d_in[17];
    const float* b1   = (const float*)d_in[18];
    const float* W2   = (const float*)d_in[19];
    const float* b2   = (const float*)d_in[20];
    float* out = (float*)d_out;

    float *p_bias, *p_xn, *p_q, *p_k, *p_v, *p_s, *p_o, *p_x1, *p_x1n, *p_h;
    cudaGetSymbolAddress((void**)&p_bias, g_bias);
    cudaGetSymbolAddress((void**)&p_xn, g_xn);
    cudaGetSymbolAddress((void**)&p_q, g_q);
    cudaGetSymbolAddress((void**)&p_k, g_k);
    cudaGetSymbolAddress((void**)&p_v, g_v);
    cudaGetSymbolAddress((void**)&p_s, g_scores);
    cudaGetSymbolAddress((void**)&p_o, g_o);
    cudaGetSymbolAddress((void**)&p_x1, g_x1);
    cudaGetSymbolAddress((void**)&p_x1n, g_x1n);
    cudaGetSymbolAddress((void**)&p_h, g_h);

    // 1. graph bias matrix [N,N]
    bias_kernel<<<NN, 256>>>(emb, lap, alpha, beta, p_bias);
    // 2. LN1
    ln_kernel<<<MROWS, 256>>>(x, ln1g, ln1b, p_xn);
    // 3. Q/K/V projections: C = xn @ W^T + b
    dim3 g512(DD / 128, MROWS / 128);
    gemm128<128, EPI_BIAS, false, false, 0, true><<<g512, 256>>>(
        p_xn, Wq, bq, nullptr, nullptr, p_q, MROWS, DD, DD, DD, DD, DD);
    gemm128<128, EPI_BIAS, false, false, 0, true><<<g512, 256>>>(
        p_xn, Wk, bk, nullptr, nullptr, p_k, MROWS, DD, DD, DD, DD, DD);
    gemm128<128, EPI_BIAS, false, false, 0, true><<<g512, 256>>>(
        p_xn, Wv, bv, nullptr, nullptr, p_v, MROWS, DD, DD, DD, DD, DD);
    // 4. scores = QK^T/8 + bias
    gemm128<128, EPI_SCORE, false, false, 1, true><<<dim3(NN / 128, NN / 128, BT * KH), 256>>>(
        p_q, p_k, nullptr, p_bias, nullptr, p_s, NN, NN, DH, DD, DD, NN);
    // 5. softmax rows
    softmax_kernel<<<BT * KH * NN, 256>>>(p_s);
    // 6. O = attn @ V   (B is [K,N] head slice, direct layout)
    gemm128<64, EPI_NONE, false, false, 2, false><<<dim3(1, NN / 128, BT * KH), 256>>>(
        p_s, p_v, nullptr, nullptr, nullptr, p_o, NN, DH, NN, NN, DD, DD);
    // 7. x1 = x + O @ Wo^T + bo
    gemm128<128, EPI_BIAS, false, true, 0, true><<<g512, 256>>>(
        p_o, Wo, bo, nullptr, x, p_x1, MROWS, DD, DD, DD, DD, DD);
    // 8. LN2
    ln_kernel<<<MROWS, 256>>>(p_x1, ln2g, ln2b, p_x1n);
    // 9. h = relu(x1n @ W1^T + b1)
    gemm128<128, EPI_BIAS, true, false, 0, true><<<dim3(D4 / 128, MROWS / 128), 256>>>(
        p_x1n, W1, b1, nullptr, nullptr, p_h, MROWS, D4, DD, DD, DD, D4);
    // 10. out = x1 + h @ W2^T + b2
    gemm128<128, EPI_BIAS, false, true, 0, true><<<g512, 256>>>(
        p_h, W2, b2, nullptr, p_x1, out, MROWS, DD, D4, D4, D4, DD);
}